// round 10
// baseline (speedup 1.0000x reference)
#include <cuda_runtime.h>
#include <cuda_bf16.h>
#include <math.h>

typedef __nv_bfloat16 bf16;
typedef unsigned int u32;
typedef unsigned long long u64;

#define SEQ  2048
#define HID  1024
#define INP  576
#define VOC  32001
#define G4H  4096
#define LCTA 128

// ---------------- static scratch (no runtime allocation allowed) ----------------
__device__ __align__(16) float  g_xg[(size_t)SEQ * G4H];        // 32 MB
__device__ __align__(16) bf16   g_x[(size_t)SEQ * INP];
__device__ __align__(16) bf16   g_Wih[(size_t)G4H * INP];
__device__ __align__(16) bf16   g_hs[(size_t)SEQ * HID];
__device__ __align__(16) bf16   g_hsT[(size_t)HID * SEQ];
__device__ __align__(16) bf16   g_out2[(size_t)SEQ * 2 * HID];  // [hs | context] bf16
__device__ __align__(16) float  g_E[(size_t)SEQ * SEQ];         // 16 MB energies
__device__ __align__(16) bf16   g_attn[(size_t)SEQ * SEQ];      // 8 MB
__device__ __align__(16) bf16   g_Wfc[(size_t)VOC * 2 * HID];   // 131 MB
__device__ __align__(16) float  g_hvec[2][HID];
__device__ u32 g_bar;

// ---------------- init ----------------
__global__ void k_init() {
    int t = threadIdx.x;
    if (t == 0) g_bar = 0u;
    for (int i = t; i < HID; i += blockDim.x) { g_hvec[0][i] = 0.f; g_hvec[1][i] = 0.f; }
}

// ---------------- fp32 -> bf16 converters ----------------
__global__ void k_cvt_wfc(const float4* __restrict__ src) {
    const size_t n4 = (size_t)VOC * 2 * HID / 4;
    __nv_bfloat162* dst = reinterpret_cast<__nv_bfloat162*>(g_Wfc);
    for (size_t i = (size_t)blockIdx.x * blockDim.x + threadIdx.x; i < n4;
         i += (size_t)gridDim.x * blockDim.x) {
        float4 v = src[i];
        dst[2*i]   = __floats2bfloat162_rn(v.x, v.y);
        dst[2*i+1] = __floats2bfloat162_rn(v.z, v.w);
    }
}
__global__ void k_cvt_wih(const float4* __restrict__ src) {
    const size_t n4 = (size_t)G4H * INP / 4;
    __nv_bfloat162* dst = reinterpret_cast<__nv_bfloat162*>(g_Wih);
    for (size_t i = (size_t)blockIdx.x * blockDim.x + threadIdx.x; i < n4;
         i += (size_t)gridDim.x * blockDim.x) {
        float4 v = src[i];
        dst[2*i]   = __floats2bfloat162_rn(v.x, v.y);
        dst[2*i+1] = __floats2bfloat162_rn(v.z, v.w);
    }
}

// ---------------- embedding gather -> bf16 x ----------------
__global__ void k_embed(const int* __restrict__ loc, const int* __restrict__ tim,
                        const float* __restrict__ el, const float* __restrict__ et) {
    int t = blockIdx.x;
    int l = loc[t], m = tim[t];
    const float* pl = el + (size_t)l * 512;
    const float* pt = et + (size_t)m * 64;
    bf16* x = g_x + (size_t)t * INP;
    for (int k = threadIdx.x; k < INP; k += blockDim.x)
        x[k] = __float2bfloat16(k < 512 ? pl[k] : pt[k - 512]);
}

// ---------------- mma / ldmatrix / cp.async primitives ----------------
__device__ __forceinline__ void mma16816(float* c, const u32* a, const u32* b) {
    asm volatile(
        "mma.sync.aligned.m16n8k16.row.col.f32.bf16.bf16.f32 "
        "{%0,%1,%2,%3}, {%4,%5,%6,%7}, {%8,%9}, {%0,%1,%2,%3};\n"
        : "+f"(c[0]), "+f"(c[1]), "+f"(c[2]), "+f"(c[3])
        : "r"(a[0]), "r"(a[1]), "r"(a[2]), "r"(a[3]), "r"(b[0]), "r"(b[1]));
}
__device__ __forceinline__ void ldsm4(u32& r0, u32& r1, u32& r2, u32& r3, u32 saddr) {
    asm volatile("ldmatrix.sync.aligned.m8n8.x4.shared.b16 {%0,%1,%2,%3}, [%4];\n"
                 : "=r"(r0), "=r"(r1), "=r"(r2), "=r"(r3) : "r"(saddr));
}
__device__ __forceinline__ void cp16(void* dst, const void* src, int srcsize) {
    u32 d = (u32)__cvta_generic_to_shared(dst);
    asm volatile("cp.async.cg.shared.global [%0], [%1], 16, %2;\n"
                 :: "r"(d), "l"(src), "r"(srcsize));
}
#define CP_COMMIT() asm volatile("cp.async.commit_group;\n" ::: "memory")

// ---------------- bf16 mma GEMM:  C[M,N] = A[M,K] * B[N,K]^T (+epilogue) ----------------
template<int MODE, int M, int N, int K>
__global__ __launch_bounds__(256, 2) void k_gemm(float* __restrict__ Cout,
                                                 const float* __restrict__ bias1,
                                                 const float* __restrict__ bias2) {
    const bf16* A; const bf16* B;
    if      (MODE == 0) { A = g_x;    B = g_Wih; }
    else if (MODE == 1) { A = g_hs;   B = g_hs;  }
    else if (MODE == 2) { A = g_attn; B = g_hsT; }
    else                { A = g_out2; B = g_Wfc; }

    __shared__ __align__(16) uint4 smT[2][2][512];

    int tid  = threadIdx.x;
    int bm   = blockIdx.x * 128;   // x fastest: CTAs sharing a B tile run adjacently
    int bn   = blockIdx.y * 128;
    int warp = tid >> 5, lane = tid & 31;
    int wm   = (warp & 3) * 32;
    int wn   = (warp >> 2) * 64;
    int r = lane >> 2, q = lane & 3;

    float acc[2][8][4];
    #pragma unroll
    for (int i = 0; i < 2; i++)
        #pragma unroll
        for (int j = 0; j < 8; j++)
            #pragma unroll
            for (int k = 0; k < 4; k++) acc[i][j][k] = 0.f;

    int lrow = tid >> 2;
    int lc   = tid & 3;

    u32 smBase = (u32)__cvta_generic_to_shared(&smT[0][0][0]);
    int l15 = lane & 15, lhi = lane >> 4;
    u32 aAddr[2][2], bAddr[4][2];
    #pragma unroll
    for (int mt = 0; mt < 2; mt++) {
        int row = wm + mt * 16 + l15;
        int swz = (row >> 1) & 3;
        #pragma unroll
        for (int kh = 0; kh < 2; kh++)
            aAddr[mt][kh] = smBase + (u32)(row * 4 + ((kh * 2 + lhi) ^ swz)) * 16;
    }
    #pragma unroll
    for (int g = 0; g < 4; g++) {
        int row = wn + g * 16 + l15;
        int swz = (row >> 1) & 3;
        #pragma unroll
        for (int kh = 0; kh < 2; kh++)
            bAddr[g][kh] = smBase + 8192u + (u32)(row * 4 + ((kh * 2 + lhi) ^ swz)) * 16;
    }

    const int ITERS = K / 32;

    auto loadStage = [&](int it, int st) {
        int k0 = it * 32;
        #pragma unroll
        for (int p = 0; p < 2; p++) {
            int row = lrow + p * 64;
            int sidx = row * 4 + (lc ^ ((row >> 1) & 3));
            cp16(&smT[st][0][sidx], A + (size_t)(bm + row) * K + k0 + lc * 8, 16);
            if (MODE == 3) {
                bool ok = (bn + row) < N;
                const bf16* gb = ok ? (B + (size_t)(bn + row) * K + k0 + lc * 8) : B;
                cp16(&smT[st][1][sidx], gb, ok ? 16 : 0);
            } else {
                cp16(&smT[st][1][sidx], B + (size_t)(bn + row) * K + k0 + lc * 8, 16);
            }
        }
    };

    loadStage(0, 0);
    CP_COMMIT();

    for (int it = 0; it < ITERS; it++) {
        int st = it & 1;
        if (it + 1 < ITERS) {
            loadStage(it + 1, st ^ 1);
            CP_COMMIT();
            asm volatile("cp.async.wait_group 1;\n" ::: "memory");
        } else {
            asm volatile("cp.async.wait_group 0;\n" ::: "memory");
        }
        __syncthreads();

        u32 stOff = (u32)st * 16384u;
        #pragma unroll
        for (int kh = 0; kh < 2; kh++) {
            u32 a[2][4];
            ldsm4(a[0][0], a[0][1], a[0][2], a[0][3], aAddr[0][kh] + stOff);
            ldsm4(a[1][0], a[1][1], a[1][2], a[1][3], aAddr[1][kh] + stOff);
            #pragma unroll
            for (int g = 0; g < 4; g++) {
                u32 b4[4];
                ldsm4(b4[0], b4[1], b4[2], b4[3], bAddr[g][kh] + stOff);
                u32 b0[2] = { b4[0], b4[2] };
                u32 b1[2] = { b4[1], b4[3] };
                mma16816(acc[0][2 * g],     a[0], b0);
                mma16816(acc[0][2 * g + 1], a[0], b1);
                mma16816(acc[1][2 * g],     a[1], b0);
                mma16816(acc[1][2 * g + 1], a[1], b1);
            }
        }
        __syncthreads();
    }

    #pragma unroll
    for (int mt = 0; mt < 2; mt++) {
        #pragma unroll
        for (int nt = 0; nt < 8; nt++) {
            int row = bm + wm + mt * 16 + r;
            int col = bn + wn + nt * 8 + 2 * q;
            float* a = acc[mt][nt];
            if (MODE == 0) {
                float b0 = bias1[col] + bias2[col];
                float b1 = bias1[col + 1] + bias2[col + 1];
                g_xg[(size_t)row * N + col]           = a[0] + b0;
                g_xg[(size_t)row * N + col + 1]       = a[1] + b1;
                g_xg[(size_t)(row + 8) * N + col]     = a[2] + b0;
                g_xg[(size_t)(row + 8) * N + col + 1] = a[3] + b1;
            } else if (MODE == 1) {
                g_E[(size_t)row * N + col]           = a[0];
                g_E[(size_t)row * N + col + 1]       = a[1];
                g_E[(size_t)(row + 8) * N + col]     = a[2];
                g_E[(size_t)(row + 8) * N + col + 1] = a[3];
            } else if (MODE == 2) {
                g_out2[(size_t)row * 2048 + 1024 + col]           = __float2bfloat16(a[0]);
                g_out2[(size_t)row * 2048 + 1024 + col + 1]       = __float2bfloat16(a[1]);
                g_out2[(size_t)(row + 8) * 2048 + 1024 + col]     = __float2bfloat16(a[2]);
                g_out2[(size_t)(row + 8) * 2048 + 1024 + col + 1] = __float2bfloat16(a[3]);
            } else {
                if (col < N) {
                    float bb = bias1[col];
                    Cout[(size_t)row * N + col]       = a[0] + bb;
                    Cout[(size_t)(row + 8) * N + col] = a[2] + bb;
                }
                if (col + 1 < N) {
                    float bb = bias1[col + 1];
                    Cout[(size_t)row * N + col + 1]       = a[1] + bb;
                    Cout[(size_t)(row + 8) * N + col + 1] = a[3] + bb;
                }
            }
        }
    }
}

// ---------------- persistent LSTM scan ----------------
__device__ __forceinline__ float tanh_fast(float x) {
    float y;
    asm("tanh.approx.f32 %0, %1;" : "=f"(y) : "f"(x));
    return y;
}
__device__ __forceinline__ float sig_fast(float x) {
    // sigmoid(x) = 0.5*tanh(0.5x) + 0.5  (single MUFU op)
    return fmaf(0.5f, tanh_fast(0.5f * x), 0.5f);
}
__device__ __forceinline__ void fma2(u64& acc, u64 a, u64 b) {
    asm("fma.rn.f32x2 %0, %1, %2, %0;" : "+l"(acc) : "l"(a), "l"(b));
}

// 128 CTAs x 256 threads. CTA b owns h-indices [8b, 8b+8) => 32 rows of W_hh.
// Weights packed as f32x2 in registers (64 u64 regs/thread -> fma.rn.f32x2).
// Sync per step: [acquire-poll by each warp's lane0] -> stage h -> BAR ->
// matvec + shfl reduce -> BAR -> warp0 gates + h store -> syncwarp ->
// tid0 red.release.gpu.add. Only 2 block barriers per step.
__global__ __launch_bounds__(256, 1) void k_lstm(const float* __restrict__ W_hh) {
    int b   = blockIdx.x;
    int tid = threadIdx.x;
    int rg  = tid >> 5;
    int ksl = tid & 31;

    // w2[i][kk] covers k = {2*ksl + 64*kk, +1}
    u64 w2[4][16];
    #pragma unroll
    for (int i = 0; i < 4; i++) {
        int rr   = rg * 4 + i;
        int grow = (rr >> 3) * HID + b * 8 + (rr & 7);
        const float* wr = W_hh + (size_t)grow * HID;
        #pragma unroll
        for (int kk = 0; kk < 16; kk++) {
            float2 v = make_float2(wr[2 * ksl + 64 * kk], wr[2 * ksl + 64 * kk + 1]);
            w2[i][kk] = *(u64*)&v;
        }
    }

    __shared__ float h_s[HID];
    __shared__ float z_s[32];
    float c_state = 0.f;
    int gb = b * 8 + tid;   // valid for tid < 8

    for (int t = 0; t < SEQ; t++) {
        int cur = t & 1;

        // prefetch this step's xg gate inputs (independent of the recurrence)
        float xzi, xzf, xzg, xzo;
        if (tid < 8) {
            const float* xr = g_xg + (size_t)t * G4H + gb;
            xzi = __ldcg(xr);
            xzf = __ldcg(xr + HID);
            xzg = __ldcg(xr + 2 * HID);
            xzo = __ldcg(xr + 3 * HID);
        }

        // wait for step-t h: each warp's lane0 acquire-polls, warp-sync broadcasts
        if (t > 0) {
            u32 target = (u32)t * (u32)LCTA;
            if (ksl == 0) {
                u32 v;
                do {
                    asm volatile("ld.acquire.gpu.global.u32 %0, [%1];"
                                 : "=r"(v) : "l"(&g_bar) : "memory");
                } while (v < target);
            }
            __syncwarp();
        }

        // stage h (L2-fresh) into smem
        float4 hv = __ldcg((const float4*)&g_hvec[cur][tid * 4]);
        *(float4*)&h_s[tid * 4] = hv;
        __syncthreads();

        // matvec with packed f32x2 FMA; lane ksl handles k pairs {2ksl+64kk}
        u64 acc[4] = {0ull, 0ull, 0ull, 0ull};
        #pragma unroll
        for (int kk = 0; kk < 16; kk++) {
            u64 h2 = *(const u64*)&h_s[2 * ksl + 64 * kk];
            fma2(acc[0], w2[0][kk], h2);
            fma2(acc[1], w2[1][kk], h2);
            fma2(acc[2], w2[2][kk], h2);
            fma2(acc[3], w2[3][kk], h2);
        }
        float a0 = __int_as_float((u32)acc[0]) + __int_as_float((u32)(acc[0] >> 32));
        float a1 = __int_as_float((u32)acc[1]) + __int_as_float((u32)(acc[1] >> 32));
        float a2 = __int_as_float((u32)acc[2]) + __int_as_float((u32)(acc[2] >> 32));
        float a3 = __int_as_float((u32)acc[3]) + __int_as_float((u32)(acc[3] >> 32));
        #pragma unroll
        for (int off = 16; off; off >>= 1) {
            a0 += __shfl_xor_sync(0xffffffffu, a0, off);
            a1 += __shfl_xor_sync(0xffffffffu, a1, off);
            a2 += __shfl_xor_sync(0xffffffffu, a2, off);
            a3 += __shfl_xor_sync(0xffffffffu, a3, off);
        }
        if (ksl == 0) {
            z_s[rg * 4 + 0] = a0; z_s[rg * 4 + 1] = a1;
            z_s[rg * 4 + 2] = a2; z_s[rg * 4 + 3] = a3;
        }
        __syncthreads();

        if (rg == 0) {
            if (tid < 8) {
                float zi = z_s[tid]      + xzi;
                float zf = z_s[8 + tid]  + xzf;
                float zg = z_s[16 + tid] + xzg;
                float zo = z_s[24 + tid] + xzo;
                c_state = sig_fast(zf) * c_state + sig_fast(zi) * tanh_fast(zg);
                float h = sig_fast(zo) * tanh_fast(c_state);
                g_hvec[cur ^ 1][gb] = h;
                bf16 hb = __float2bfloat16(h);
                g_hs[(size_t)t * HID + gb]         = hb;
                g_hsT[(size_t)gb * SEQ + t]        = hb;
                g_out2[(size_t)t * (2 * HID) + gb] = hb;
            }
            __syncwarp();   // orders warp-0 h stores before the release
            if (tid == 0)
                asm volatile("red.release.gpu.global.add.u32 [%0], %1;"
                             :: "l"(&g_bar), "r"(1u) : "memory");
        }
    }
}

// ---------------- causal softmax over energies -> bf16 attn ----------------
__global__ __launch_bounds__(256) void k_attn_softmax() {
    int i = blockIdx.x;
    int tid = threadIdx.x;
    int len = i + 1;
    const float* row = g_E + (size_t)i * SEQ;
    __shared__ float sm[8];

    float mx = -1e30f;
    for (int j = tid; j < len; j += 256) mx = fmaxf(mx, row[j]);
    #pragma unroll
    for (int o = 16; o; o >>= 1) mx = fmaxf(mx, __shfl_xor_sync(0xffffffffu, mx, o));
    if ((tid & 31) == 0) sm[tid >> 5] = mx;
    __syncthreads();
    mx = sm[0];
    #pragma unroll
    for (int wI = 1; wI < 8; wI++) mx = fmaxf(mx, sm[wI]);
    __syncthreads();

    float s = 0.f;
    for (int j = tid; j < len; j += 256) s += __expf(row[j] - mx);
    #pragma unroll
    for (int o = 16; o; o >>= 1) s += __shfl_xor_sync(0xffffffffu, s, o);
    if ((tid & 31) == 0) sm[tid >> 5] = s;
    __syncthreads();
    s = 0.f;
    #pragma unroll
    for (int wI = 0; wI < 8; wI++) s += sm[wI];
    float inv = 1.f / s;

    bf16* arow = g_attn + (size_t)i * SEQ;
    for (int j = tid; j < SEQ; j += 256)
        arow[j] = __float2bfloat16(j < len ? __expf(row[j] - mx) * inv : 0.f);
}

// ---------------- log_softmax on d_out rows (row cached in dynamic smem) ----------------
__global__ __launch_bounds__(256) void k_logsoftmax(float* __restrict__ Y) {
    extern __shared__ float rowbuf[];
    int i = blockIdx.x;
    int tid = threadIdx.x;
    float* row = Y + (size_t)i * VOC;
    __shared__ float sm[8];

    float mx = -1e30f;
    for (int j = tid; j < VOC; j += 256) {
        float v = row[j];
        rowbuf[j] = v;
        mx = fmaxf(mx, v);
    }
    #pragma unroll
    for (int o = 16; o; o >>= 1) mx = fmaxf(mx, __shfl_xor_sync(0xffffffffu, mx, o));
    if ((tid & 31) == 0) sm[tid >> 5] = mx;
    __syncthreads();
    mx = sm[0];
    #pragma unroll
    for (int wI = 1; wI < 8; wI++) mx = fmaxf(mx, sm[wI]);
    __syncthreads();

    float s = 0.f;
    for (int j = tid; j < VOC; j += 256) s += __expf(rowbuf[j] - mx);
    #pragma unroll
    for (int o = 16; o; o >>= 1) s += __shfl_xor_sync(0xffffffffu, s, o);
    if ((tid & 31) == 0) sm[tid >> 5] = s;
    __syncthreads();
    s = 0.f;
    #pragma unroll
    for (int wI = 0; wI < 8; wI++) s += sm[wI];
    float ls = mx + logf(s);

    for (int j = tid; j < VOC; j += 256) row[j] = rowbuf[j] - ls;
}

// ---------------- driver ----------------
extern "C" void kernel_launch(void* const* d_in, const int* in_sizes, int n_in,
                              void* d_out, int out_size) {
    const int*   loc    = (const int*)d_in[0];
    const int*   tim    = (const int*)d_in[1];
    const float* embloc = (const float*)d_in[2];
    const float* embtim = (const float*)d_in[3];
    const float* Wih    = (const float*)d_in[4];
    const float* Whh    = (const float*)d_in[5];
    const float* bih    = (const float*)d_in[6];
    const float* bhh    = (const float*)d_in[7];
    const float* Wfc    = (const float*)d_in[8];
    const float* bfc    = (const float*)d_in[9];
    float* out = (float*)d_out;

    cudaFuncSetAttribute(k_logsoftmax, cudaFuncAttributeMaxDynamicSharedMemorySize, 131072);

    k_init<<<1, 256>>>();
    k_cvt_wfc<<<2048, 256>>>((const float4*)Wfc);
    k_cvt_wih<<<512, 256>>>((const float4*)Wih);
    k_embed<<<SEQ, 128>>>(loc, tim, embloc, embtim);

    // xg = x @ Wih^T + (b_ih + b_hh)   [2048 x 4096], K=576
    k_gemm<0, SEQ, G4H, INP><<<dim3(SEQ / 128, G4H / 128), 256>>>(nullptr, bih, bhh);

    // sequential scan (persistent, 128 CTAs)
    k_lstm<<<LCTA, 256>>>(Whh);

    // energies = hs @ hs^T   [2048 x 2048], K=1024
    k_gemm<1, SEQ, SEQ, HID><<<dim3(SEQ / 128, SEQ / 128), 256>>>(nullptr, nullptr, nullptr);
    k_attn_softmax<<<SEQ, 256>>>();

    // context = attn @ hs  -> bf16 into g_out2[:, 1024:2048], K=2048
    k_gemm<2, SEQ, HID, SEQ><<<dim3(SEQ / 128, HID / 128), 256>>>(nullptr, nullptr, nullptr);

    // y = out2 @ Wfc^T + b_fc   [2048 x 32001], K=2048
    k_gemm<3, SEQ, VOC, 2 * HID><<<dim3(SEQ / 128, (VOC + 127) / 128), 256>>>(out, bfc, nullptr);

    k_logsoftmax<<<SEQ, 256, 131072>>>(out);
}

// round 11
// speedup vs baseline: 1.7654x; 1.7654x over previous
#include <cuda_runtime.h>
#include <cuda_bf16.h>
#include <math.h>

typedef __nv_bfloat16 bf16;
typedef unsigned int u32;

#define SEQ  2048
#define HID  1024
#define INP  576
#define VOC  32001
#define G4H  4096
#define LCTA 128

// ---------------- static scratch (no runtime allocation allowed) ----------------
__device__ __align__(16) float  g_xg[(size_t)SEQ * G4H];        // 32 MB
__device__ __align__(16) bf16   g_x[(size_t)SEQ * INP];
__device__ __align__(16) bf16   g_Wih[(size_t)G4H * INP];
__device__ __align__(16) bf16   g_hs[(size_t)SEQ * HID];
__device__ __align__(16) bf16   g_hsT[(size_t)HID * SEQ];
__device__ __align__(16) bf16   g_out2[(size_t)SEQ * 2 * HID];  // [hs | context] bf16
__device__ __align__(16) float  g_E[(size_t)SEQ * SEQ];         // 16 MB energies
__device__ __align__(16) bf16   g_attn[(size_t)SEQ * SEQ];      // 8 MB
__device__ __align__(16) bf16   g_Wfc[(size_t)VOC * 2 * HID];   // 131 MB
__device__ __align__(16) float  g_hvec[2][HID];
__device__ u32 g_bar;

// ---------------- init ----------------
__global__ void k_init() {
    int t = threadIdx.x;
    if (t == 0) g_bar = 0u;
    for (int i = t; i < HID; i += blockDim.x) { g_hvec[0][i] = 0.f; g_hvec[1][i] = 0.f; }
}

// ---------------- fp32 -> bf16 converters ----------------
__global__ void k_cvt_wfc(const float4* __restrict__ src) {
    const size_t n4 = (size_t)VOC * 2 * HID / 4;
    __nv_bfloat162* dst = reinterpret_cast<__nv_bfloat162*>(g_Wfc);
    for (size_t i = (size_t)blockIdx.x * blockDim.x + threadIdx.x; i < n4;
         i += (size_t)gridDim.x * blockDim.x) {
        float4 v = src[i];
        dst[2*i]   = __floats2bfloat162_rn(v.x, v.y);
        dst[2*i+1] = __floats2bfloat162_rn(v.z, v.w);
    }
}
__global__ void k_cvt_wih(const float4* __restrict__ src) {
    const size_t n4 = (size_t)G4H * INP / 4;
    __nv_bfloat162* dst = reinterpret_cast<__nv_bfloat162*>(g_Wih);
    for (size_t i = (size_t)blockIdx.x * blockDim.x + threadIdx.x; i < n4;
         i += (size_t)gridDim.x * blockDim.x) {
        float4 v = src[i];
        dst[2*i]   = __floats2bfloat162_rn(v.x, v.y);
        dst[2*i+1] = __floats2bfloat162_rn(v.z, v.w);
    }
}

// ---------------- embedding gather -> bf16 x ----------------
__global__ void k_embed(const int* __restrict__ loc, const int* __restrict__ tim,
                        const float* __restrict__ el, const float* __restrict__ et) {
    int t = blockIdx.x;
    int l = loc[t], m = tim[t];
    const float* pl = el + (size_t)l * 512;
    const float* pt = et + (size_t)m * 64;
    bf16* x = g_x + (size_t)t * INP;
    for (int k = threadIdx.x; k < INP; k += blockDim.x)
        x[k] = __float2bfloat16(k < 512 ? pl[k] : pt[k - 512]);
}

// ---------------- mma / ldmatrix / cp.async primitives ----------------
__device__ __forceinline__ void mma16816(float* c, const u32* a, const u32* b) {
    asm volatile(
        "mma.sync.aligned.m16n8k16.row.col.f32.bf16.bf16.f32 "
        "{%0,%1,%2,%3}, {%4,%5,%6,%7}, {%8,%9}, {%0,%1,%2,%3};\n"
        : "+f"(c[0]), "+f"(c[1]), "+f"(c[2]), "+f"(c[3])
        : "r"(a[0]), "r"(a[1]), "r"(a[2]), "r"(a[3]), "r"(b[0]), "r"(b[1]));
}
__device__ __forceinline__ void ldsm4(u32& r0, u32& r1, u32& r2, u32& r3, u32 saddr) {
    asm volatile("ldmatrix.sync.aligned.m8n8.x4.shared.b16 {%0,%1,%2,%3}, [%4];\n"
                 : "=r"(r0), "=r"(r1), "=r"(r2), "=r"(r3) : "r"(saddr));
}
__device__ __forceinline__ void cp16(void* dst, const void* src, int srcsize) {
    u32 d = (u32)__cvta_generic_to_shared(dst);
    asm volatile("cp.async.cg.shared.global [%0], [%1], 16, %2;\n"
                 :: "r"(d), "l"(src), "r"(srcsize));
}
#define CP_COMMIT() asm volatile("cp.async.commit_group;\n" ::: "memory")

// ---------------- bf16 mma GEMM:  C[M,N] = A[M,K] * B[N,K]^T (+epilogue) ----------------
template<int MODE, int M, int N, int K>
__global__ __launch_bounds__(256, 2) void k_gemm(float* __restrict__ Cout,
                                                 const float* __restrict__ bias1,
                                                 const float* __restrict__ bias2) {
    const bf16* A; const bf16* B;
    if      (MODE == 0) { A = g_x;    B = g_Wih; }
    else if (MODE == 1) { A = g_hs;   B = g_hs;  }
    else if (MODE == 2) { A = g_attn; B = g_hsT; }
    else                { A = g_out2; B = g_Wfc; }

    __shared__ __align__(16) uint4 smT[2][2][512];

    int tid  = threadIdx.x;
    int bm   = blockIdx.x * 128;   // x fastest: CTAs sharing a B tile run adjacently
    int bn   = blockIdx.y * 128;
    int warp = tid >> 5, lane = tid & 31;
    int wm   = (warp & 3) * 32;
    int wn   = (warp >> 2) * 64;
    int r = lane >> 2, q = lane & 3;

    float acc[2][8][4];
    #pragma unroll
    for (int i = 0; i < 2; i++)
        #pragma unroll
        for (int j = 0; j < 8; j++)
            #pragma unroll
            for (int k = 0; k < 4; k++) acc[i][j][k] = 0.f;

    int lrow = tid >> 2;
    int lc   = tid & 3;

    u32 smBase = (u32)__cvta_generic_to_shared(&smT[0][0][0]);
    int l15 = lane & 15, lhi = lane >> 4;
    u32 aAddr[2][2], bAddr[4][2];
    #pragma unroll
    for (int mt = 0; mt < 2; mt++) {
        int row = wm + mt * 16 + l15;
        int swz = (row >> 1) & 3;
        #pragma unroll
        for (int kh = 0; kh < 2; kh++)
            aAddr[mt][kh] = smBase + (u32)(row * 4 + ((kh * 2 + lhi) ^ swz)) * 16;
    }
    #pragma unroll
    for (int g = 0; g < 4; g++) {
        int row = wn + g * 16 + l15;
        int swz = (row >> 1) & 3;
        #pragma unroll
        for (int kh = 0; kh < 2; kh++)
            bAddr[g][kh] = smBase + 8192u + (u32)(row * 4 + ((kh * 2 + lhi) ^ swz)) * 16;
    }

    const int ITERS = K / 32;

    auto loadStage = [&](int it, int st) {
        int k0 = it * 32;
        #pragma unroll
        for (int p = 0; p < 2; p++) {
            int row = lrow + p * 64;
            int sidx = row * 4 + (lc ^ ((row >> 1) & 3));
            cp16(&smT[st][0][sidx], A + (size_t)(bm + row) * K + k0 + lc * 8, 16);
            if (MODE == 3) {
                bool ok = (bn + row) < N;
                const bf16* gb = ok ? (B + (size_t)(bn + row) * K + k0 + lc * 8) : B;
                cp16(&smT[st][1][sidx], gb, ok ? 16 : 0);
            } else {
                cp16(&smT[st][1][sidx], B + (size_t)(bn + row) * K + k0 + lc * 8, 16);
            }
        }
    };

    loadStage(0, 0);
    CP_COMMIT();

    for (int it = 0; it < ITERS; it++) {
        int st = it & 1;
        if (it + 1 < ITERS) {
            loadStage(it + 1, st ^ 1);
            CP_COMMIT();
            asm volatile("cp.async.wait_group 1;\n" ::: "memory");
        } else {
            asm volatile("cp.async.wait_group 0;\n" ::: "memory");
        }
        __syncthreads();

        u32 stOff = (u32)st * 16384u;
        #pragma unroll
        for (int kh = 0; kh < 2; kh++) {
            u32 a[2][4];
            ldsm4(a[0][0], a[0][1], a[0][2], a[0][3], aAddr[0][kh] + stOff);
            ldsm4(a[1][0], a[1][1], a[1][2], a[1][3], aAddr[1][kh] + stOff);
            #pragma unroll
            for (int g = 0; g < 4; g++) {
                u32 b4[4];
                ldsm4(b4[0], b4[1], b4[2], b4[3], bAddr[g][kh] + stOff);
                u32 b0[2] = { b4[0], b4[2] };
                u32 b1[2] = { b4[1], b4[3] };
                mma16816(acc[0][2 * g],     a[0], b0);
                mma16816(acc[0][2 * g + 1], a[0], b1);
                mma16816(acc[1][2 * g],     a[1], b0);
                mma16816(acc[1][2 * g + 1], a[1], b1);
            }
        }
        __syncthreads();
    }

    #pragma unroll
    for (int mt = 0; mt < 2; mt++) {
        #pragma unroll
        for (int nt = 0; nt < 8; nt++) {
            int row = bm + wm + mt * 16 + r;
            int col = bn + wn + nt * 8 + 2 * q;
            float* a = acc[mt][nt];
            if (MODE == 0) {
                float b0 = bias1[col] + bias2[col];
                float b1 = bias1[col + 1] + bias2[col + 1];
                g_xg[(size_t)row * N + col]           = a[0] + b0;
                g_xg[(size_t)row * N + col + 1]       = a[1] + b1;
                g_xg[(size_t)(row + 8) * N + col]     = a[2] + b0;
                g_xg[(size_t)(row + 8) * N + col + 1] = a[3] + b1;
            } else if (MODE == 1) {
                g_E[(size_t)row * N + col]           = a[0];
                g_E[(size_t)row * N + col + 1]       = a[1];
                g_E[(size_t)(row + 8) * N + col]     = a[2];
                g_E[(size_t)(row + 8) * N + col + 1] = a[3];
            } else if (MODE == 2) {
                g_out2[(size_t)row * 2048 + 1024 + col]           = __float2bfloat16(a[0]);
                g_out2[(size_t)row * 2048 + 1024 + col + 1]       = __float2bfloat16(a[1]);
                g_out2[(size_t)(row + 8) * 2048 + 1024 + col]     = __float2bfloat16(a[2]);
                g_out2[(size_t)(row + 8) * 2048 + 1024 + col + 1] = __float2bfloat16(a[3]);
            } else {
                if (col < N) {
                    float bb = bias1[col];
                    Cout[(size_t)row * N + col]       = a[0] + bb;
                    Cout[(size_t)(row + 8) * N + col] = a[2] + bb;
                }
                if (col + 1 < N) {
                    float bb = bias1[col + 1];
                    Cout[(size_t)row * N + col + 1]       = a[1] + bb;
                    Cout[(size_t)(row + 8) * N + col + 1] = a[3] + bb;
                }
            }
        }
    }
}

// ---------------- persistent LSTM scan ----------------
__device__ __forceinline__ float tanh_fast(float x) {
    float y;
    asm("tanh.approx.f32 %0, %1;" : "=f"(y) : "f"(x));
    return y;
}
__device__ __forceinline__ float sig_fast(float x) {
    // sigmoid(x) = 0.5*tanh(0.5x) + 0.5  (single MUFU op)
    return fmaf(0.5f, tanh_fast(0.5f * x), 0.5f);
}

// 128 CTAs x 256 threads. CTA b owns h-indices [8b, 8b+8) => 32 rows of W_hh
// (4 gates x 8). Weights in fp32 registers (128/thread), scalar FFMA matvec
// (proven round-9 code path). Sync per step (3 block BARs, single poller):
//   tid0 acquire-poll -> BAR -> stage h -> BAR -> matvec+reduce+z_s -> BAR ->
//   warp0 gates + h store -> syncwarp -> tid0 red.release.
__global__ __launch_bounds__(256, 1) void k_lstm(const float* __restrict__ W_hh) {
    int b   = blockIdx.x;
    int tid = threadIdx.x;
    int rg  = tid >> 5;
    int ksl = tid & 31;

    float w[4][32];
    #pragma unroll
    for (int i = 0; i < 4; i++) {
        int rr   = rg * 4 + i;
        int grow = (rr >> 3) * HID + b * 8 + (rr & 7);
        const float* wr = W_hh + (size_t)grow * HID;
        #pragma unroll
        for (int kk = 0; kk < 32; kk++) w[i][kk] = wr[ksl + 32 * kk];
    }

    __shared__ float h_s[HID];
    __shared__ float z_s[32];
    float c_state = 0.f;
    int gb = b * 8 + tid;   // valid for tid < 8

    for (int t = 0; t < SEQ; t++) {
        int cur = t & 1;

        // prefetch this step's xg gate inputs (independent of the recurrence)
        float xzi, xzf, xzg, xzo;
        if (tid < 8) {
            const float* xr = g_xg + (size_t)t * G4H + gb;
            xzi = __ldcg(xr);
            xzf = __ldcg(xr + HID);
            xzg = __ldcg(xr + 2 * HID);
            xzo = __ldcg(xr + 3 * HID);
        }

        // single poller waits until every CTA released step t-1
        if (t > 0 && tid == 0) {
            u32 target = (u32)t * (u32)LCTA;
            u32 v;
            do {
                asm volatile("ld.acquire.gpu.global.u32 %0, [%1];"
                             : "=r"(v) : "l"(&g_bar) : "memory");
            } while (v < target);
        }
        __syncthreads();   // BAR A: release poll result to whole CTA

        // stage h (L2-fresh) into smem
        float4 hv = __ldcg((const float4*)&g_hvec[cur][tid * 4]);
        *(float4*)&h_s[tid * 4] = hv;
        __syncthreads();   // BAR B

        float a0 = 0.f, a1 = 0.f, a2 = 0.f, a3 = 0.f;
        #pragma unroll
        for (int kk = 0; kk < 32; kk++) {
            float h = h_s[ksl + 32 * kk];   // bank = ksl : conflict-free
            a0 = fmaf(w[0][kk], h, a0);
            a1 = fmaf(w[1][kk], h, a1);
            a2 = fmaf(w[2][kk], h, a2);
            a3 = fmaf(w[3][kk], h, a3);
        }
        #pragma unroll
        for (int off = 16; off; off >>= 1) {
            a0 += __shfl_xor_sync(0xffffffffu, a0, off);
            a1 += __shfl_xor_sync(0xffffffffu, a1, off);
            a2 += __shfl_xor_sync(0xffffffffu, a2, off);
            a3 += __shfl_xor_sync(0xffffffffu, a3, off);
        }
        if (ksl == 0) {
            z_s[rg * 4 + 0] = a0; z_s[rg * 4 + 1] = a1;
            z_s[rg * 4 + 2] = a2; z_s[rg * 4 + 3] = a3;
        }
        __syncthreads();   // BAR C

        if (rg == 0) {
            if (tid < 8) {
                float zi = z_s[tid]      + xzi;
                float zf = z_s[8 + tid]  + xzf;
                float zg = z_s[16 + tid] + xzg;
                float zo = z_s[24 + tid] + xzo;
                c_state = sig_fast(zf) * c_state + sig_fast(zi) * tanh_fast(zg);
                float h = sig_fast(zo) * tanh_fast(c_state);
                g_hvec[cur ^ 1][gb] = h;
                bf16 hb = __float2bfloat16(h);
                g_hs[(size_t)t * HID + gb]         = hb;
                g_hsT[(size_t)gb * SEQ + t]        = hb;
                g_out2[(size_t)t * (2 * HID) + gb] = hb;
            }
            __syncwarp();   // orders warp-0 h stores before the release
            if (tid == 0)
                asm volatile("red.release.gpu.global.add.u32 [%0], %1;"
                             :: "l"(&g_bar), "r"(1u) : "memory");
        }
        // non-zero warps proceed to next iteration; BAR A gates them behind
        // tid0's poll, and z_s/h_s rewrites are fenced by BAR B/C.
    }
}

// ---------------- causal softmax over energies -> bf16 attn ----------------
__global__ __launch_bounds__(256) void k_attn_softmax() {
    int i = blockIdx.x;
    int tid = threadIdx.x;
    int len = i + 1;
    const float* row = g_E + (size_t)i * SEQ;
    __shared__ float sm[8];

    float mx = -1e30f;
    for (int j = tid; j < len; j += 256) mx = fmaxf(mx, row[j]);
    #pragma unroll
    for (int o = 16; o; o >>= 1) mx = fmaxf(mx, __shfl_xor_sync(0xffffffffu, mx, o));
    if ((tid & 31) == 0) sm[tid >> 5] = mx;
    __syncthreads();
    mx = sm[0];
    #pragma unroll
    for (int wI = 1; wI < 8; wI++) mx = fmaxf(mx, sm[wI]);
    __syncthreads();

    float s = 0.f;
    for (int j = tid; j < len; j += 256) s += __expf(row[j] - mx);
    #pragma unroll
    for (int o = 16; o; o >>= 1) s += __shfl_xor_sync(0xffffffffu, s, o);
    if ((tid & 31) == 0) sm[tid >> 5] = s;
    __syncthreads();
    s = 0.f;
    #pragma unroll
    for (int wI = 0; wI < 8; wI++) s += sm[wI];
    float inv = 1.f / s;

    bf16* arow = g_attn + (size_t)i * SEQ;
    for (int j = tid; j < SEQ; j += 256)
        arow[j] = __float2bfloat16(j < len ? __expf(row[j] - mx) * inv : 0.f);
}

// ---------------- log_softmax on d_out rows (row cached in dynamic smem) ----------------
__global__ __launch_bounds__(256) void k_logsoftmax(float* __restrict__ Y) {
    extern __shared__ float rowbuf[];
    int i = blockIdx.x;
    int tid = threadIdx.x;
    float* row = Y + (size_t)i * VOC;
    __shared__ float sm[8];

    float mx = -1e30f;
    for (int j = tid; j < VOC; j += 256) {
        float v = row[j];
        rowbuf[j] = v;
        mx = fmaxf(mx, v);
    }
    #pragma unroll
    for (int o = 16; o; o >>= 1) mx = fmaxf(mx, __shfl_xor_sync(0xffffffffu, mx, o));
    if ((tid & 31) == 0) sm[tid >> 5] = mx;
    __syncthreads();
    mx = sm[0];
    #pragma unroll
    for (int wI = 1; wI < 8; wI++) mx = fmaxf(mx, sm[wI]);
    __syncthreads();

    float s = 0.f;
    for (int j = tid; j < VOC; j += 256) s += __expf(rowbuf[j] - mx);
    #pragma unroll
    for (int o = 16; o; o >>= 1) s += __shfl_xor_sync(0xffffffffu, s, o);
    if ((tid & 31) == 0) sm[tid >> 5] = s;
    __syncthreads();
    s = 0.f;
    #pragma unroll
    for (int wI = 0; wI < 8; wI++) s += sm[wI];
    float ls = mx + logf(s);

    for (int j = tid; j < VOC; j += 256) row[j] = rowbuf[j] - ls;
}

// ---------------- driver ----------------
extern "C" void kernel_launch(void* const* d_in, const int* in_sizes, int n_in,
                              void* d_out, int out_size) {
    const int*   loc    = (const int*)d_in[0];
    const int*   tim    = (const int*)d_in[1];
    const float* embloc = (const float*)d_in[2];
    const float* embtim = (const float*)d_in[3];
    const float* Wih    = (const float*)d_in[4];
    const float* Whh    = (const float*)d_in[5];
    const float* bih    = (const float*)d_in[6];
    const float* bhh    = (const float*)d_in[7];
    const float* Wfc    = (const float*)d_in[8];
    const float* bfc    = (const float*)d_in[9];
    float* out = (float*)d_out;

    cudaFuncSetAttribute(k_logsoftmax, cudaFuncAttributeMaxDynamicSharedMemorySize, 131072);

    k_init<<<1, 256>>>();
    k_cvt_wfc<<<2048, 256>>>((const float4*)Wfc);
    k_cvt_wih<<<512, 256>>>((const float4*)Wih);
    k_embed<<<SEQ, 128>>>(loc, tim, embloc, embtim);

    // xg = x @ Wih^T + (b_ih + b_hh)   [2048 x 4096], K=576
    k_gemm<0, SEQ, G4H, INP><<<dim3(SEQ / 128, G4H / 128), 256>>>(nullptr, bih, bhh);

    // sequential scan (persistent, 128 CTAs)
    k_lstm<<<LCTA, 256>>>(Whh);

    // energies = hs @ hs^T   [2048 x 2048], K=1024
    k_gemm<1, SEQ, SEQ, HID><<<dim3(SEQ / 128, SEQ / 128), 256>>>(nullptr, nullptr, nullptr);
    k_attn_softmax<<<SEQ, 256>>>();

    // context = attn @ hs  -> bf16 into g_out2[:, 1024:2048], K=2048
    k_gemm<2, SEQ, HID, SEQ><<<dim3(SEQ / 128, HID / 128), 256>>>(nullptr, nullptr, nullptr);

    // y = out2 @ Wfc^T + b_fc   [2048 x 32001], K=2048
    k_gemm<3, SEQ, VOC, 2 * HID><<<dim3(SEQ / 128, (VOC + 127) / 128), 256>>>(out, bfc, nullptr);

    k_logsoftmax<<<SEQ, 256, 131072>>>(out);
}